// round 2
// baseline (speedup 1.0000x reference)
#include <cuda_runtime.h>
#include <cuda_bf16.h>

#define NN 100000
#define FDIM 128
#define BM 128
#define BK 16
#define SPAD 132   // padded smem row (floats), 16B-aligned, breaks bank conflicts

// ---- scratch (device globals: allowed; no runtime allocation) ----
__device__ float g_agg[(size_t)NN * FDIM];   // (1+eps)*x + neighbor_sum
__device__ float g_h[(size_t)NN * FDIM];     // h after GEMM1 (+b1)
__device__ float g_sum[FDIM];
__device__ float g_sq[FDIM];
__device__ float g_scale[FDIM];
__device__ float g_shift[FDIM];
__device__ int   g_ei64;                     // 1 if edge_index is int64, 0 if int32

// ---------------------------------------------------------------------------
// Kernel 0: probe edge_index dtype. int64 data always lies in [0, NN);
// int32 data read as int64 fuses two indices -> value >= 2^32 w.h.p.
// ---------------------------------------------------------------------------
__global__ void detect_kernel(const long long* __restrict__ ei) {
    if (threadIdx.x == 0) {
        int ok64 = 1;
        for (int i = 0; i < 64; ++i) {
            long long v = ei[i];
            if (v < 0 || v >= NN) { ok64 = 0; break; }
        }
        g_ei64 = ok64;
    }
}

// ---------------------------------------------------------------------------
// Kernel 1: agg = (1+eps)*x ; zero BN stat accumulators
// ---------------------------------------------------------------------------
__global__ __launch_bounds__(256) void init_kernel(const float* __restrict__ x,
                                                   const float* __restrict__ eps) {
    int i = blockIdx.x * 256 + threadIdx.x;
    if (i < FDIM) { g_sum[i] = 0.f; g_sq[i] = 0.f; }
    const int total4 = NN * FDIM / 4;
    if (i < total4) {
        float c = 1.0f + __ldg(eps);
        float4 v = __ldg(((const float4*)x) + i);
        v.x *= c; v.y *= c; v.z *= c; v.w *= c;
        ((float4*)g_agg)[i] = v;
    }
}

// ---------------------------------------------------------------------------
// Kernel 2: scatter-add neighbor features. One warp per edge, float4/lane.
// ---------------------------------------------------------------------------
__global__ __launch_bounds__(256) void scatter_kernel(const float* __restrict__ x,
                                                      const void* __restrict__ ei_raw,
                                                      int E) {
    int gtid = blockIdx.x * 256 + threadIdx.x;
    int e = gtid >> 5;
    int lane = gtid & 31;
    if (e >= E) return;
    long long r, c;
    if (g_ei64) {
        const long long* ei = (const long long*)ei_raw;
        r = __ldg(&ei[e]);
        c = __ldg(&ei[E + e]);
    } else {
        const int* ei = (const int*)ei_raw;
        r = __ldg(&ei[e]);
        c = __ldg(&ei[E + e]);
    }
    if ((unsigned long long)r >= NN || (unsigned long long)c >= NN) return;
    float4 v = __ldg(((const float4*)(x + c * FDIM)) + lane);
    float* dst = g_agg + r * FDIM + lane * 4;
    asm volatile("red.global.add.v4.f32 [%0], {%1, %2, %3, %4};"
                 :: "l"(dst), "f"(v.x), "f"(v.y), "f"(v.z), "f"(v.w) : "memory");
}

// ---------------------------------------------------------------------------
// Kernel 3: GEMM1  h = agg @ W1^T + b1, fused BN stats (sum, sumsq per col)
// 128x128 block tile, 8x8 thread tile, BK=16, A/W transposed in smem.
// ---------------------------------------------------------------------------
__global__ __launch_bounds__(256) void gemm1_kernel(const float* __restrict__ W1,
                                                    const float* __restrict__ b1) {
    __shared__ float a_s[BK][SPAD];
    __shared__ float w_s[BK][SPAD];
    __shared__ float red_s[16][FDIM];

    const int tid = threadIdx.x;
    const int tx = tid & 15;     // col group
    const int ty = tid >> 4;     // row group
    const int row0 = blockIdx.x * BM;

    float acc[8][8];
#pragma unroll
    for (int i = 0; i < 8; ++i)
#pragma unroll
        for (int j = 0; j < 8; ++j) acc[i][j] = 0.f;

    for (int kt = 0; kt < FDIM; kt += BK) {
#pragma unroll
        for (int it = 0; it < 2; ++it) {
            int idx = it * 256 + tid;           // 0..511
            int r = idx >> 2;                   // 0..127
            int kk = (idx & 3) * 4;             // 0,4,8,12
            int grow = row0 + r;
            float4 v = make_float4(0.f, 0.f, 0.f, 0.f);
            if (grow < NN) v = __ldg((const float4*)&g_agg[(size_t)grow * FDIM + kt + kk]);
            a_s[kk + 0][r] = v.x; a_s[kk + 1][r] = v.y;
            a_s[kk + 2][r] = v.z; a_s[kk + 3][r] = v.w;
            int j = r;                          // W1 row (output feature)
            float4 w = __ldg((const float4*)&W1[(size_t)j * FDIM + kt + kk]);
            w_s[kk + 0][j] = w.x; w_s[kk + 1][j] = w.y;
            w_s[kk + 2][j] = w.z; w_s[kk + 3][j] = w.w;
        }
        __syncthreads();
#pragma unroll
        for (int k = 0; k < BK; ++k) {
            float4 a0 = *(const float4*)&a_s[k][ty * 8];
            float4 a1 = *(const float4*)&a_s[k][ty * 8 + 4];
            float4 w0 = *(const float4*)&w_s[k][tx * 8];
            float4 w1 = *(const float4*)&w_s[k][tx * 8 + 4];
            float ar[8] = {a0.x, a0.y, a0.z, a0.w, a1.x, a1.y, a1.z, a1.w};
            float wr[8] = {w0.x, w0.y, w0.z, w0.w, w1.x, w1.y, w1.z, w1.w};
#pragma unroll
            for (int i = 0; i < 8; ++i)
#pragma unroll
                for (int j = 0; j < 8; ++j) acc[i][j] = fmaf(ar[i], wr[j], acc[i][j]);
        }
        __syncthreads();
    }

    float bias[8];
#pragma unroll
    for (int c = 0; c < 8; ++c) bias[c] = __ldg(&b1[tx * 8 + c]);

    float psum[8], psq[8];
#pragma unroll
    for (int c = 0; c < 8; ++c) { psum[c] = 0.f; psq[c] = 0.f; }

#pragma unroll
    for (int i = 0; i < 8; ++i) {
        int grow = row0 + ty * 8 + i;
        if (grow < NN) {
            float h[8];
#pragma unroll
            for (int c = 0; c < 8; ++c) {
                h[c] = acc[i][c] + bias[c];
                psum[c] += h[c];
                psq[c] += h[c] * h[c];
            }
            float4* dst = (float4*)&g_h[(size_t)grow * FDIM + tx * 8];
            dst[0] = make_float4(h[0], h[1], h[2], h[3]);
            dst[1] = make_float4(h[4], h[5], h[6], h[7]);
        }
    }

    // block-level column reduction, then one global atomic per column
#pragma unroll
    for (int c = 0; c < 8; ++c) red_s[ty][tx * 8 + c] = psum[c];
    __syncthreads();
    for (int s = 8; s > 0; s >>= 1) {
        if (ty < s) {
#pragma unroll
            for (int c = 0; c < 8; ++c)
                red_s[ty][tx * 8 + c] += red_s[ty + s][tx * 8 + c];
        }
        __syncthreads();
    }
    if (ty == 0) {
#pragma unroll
        for (int c = 0; c < 8; ++c) atomicAdd(&g_sum[tx * 8 + c], red_s[0][tx * 8 + c]);
    }
    __syncthreads();
#pragma unroll
    for (int c = 0; c < 8; ++c) red_s[ty][tx * 8 + c] = psq[c];
    __syncthreads();
    for (int s = 8; s > 0; s >>= 1) {
        if (ty < s) {
#pragma unroll
            for (int c = 0; c < 8; ++c)
                red_s[ty][tx * 8 + c] += red_s[ty + s][tx * 8 + c];
        }
        __syncthreads();
    }
    if (ty == 0) {
#pragma unroll
        for (int c = 0; c < 8; ++c) atomicAdd(&g_sq[tx * 8 + c], red_s[0][tx * 8 + c]);
    }
}

// ---------------------------------------------------------------------------
// Kernel 4: fold BN into scale/shift:  a = h*scale + shift ; relu
// ---------------------------------------------------------------------------
__global__ void finalize_kernel(const float* __restrict__ gamma,
                                const float* __restrict__ beta) {
    int i = threadIdx.x;
    float invn = 1.0f / (float)NN;
    float mean = g_sum[i] * invn;
    float var = g_sq[i] * invn - mean * mean;
    float rstd = rsqrtf(var + 1e-5f);
    float sc = rstd * __ldg(&gamma[i]);
    g_scale[i] = sc;
    g_shift[i] = __ldg(&beta[i]) - mean * sc;
}

// ---------------------------------------------------------------------------
// Kernel 5: GEMM2  out = relu(h*scale+shift) @ W2^T + b2
// ---------------------------------------------------------------------------
__global__ __launch_bounds__(256) void gemm2_kernel(const float* __restrict__ W2,
                                                    const float* __restrict__ b2,
                                                    float* __restrict__ out) {
    __shared__ float a_s[BK][SPAD];
    __shared__ float w_s[BK][SPAD];

    const int tid = threadIdx.x;
    const int tx = tid & 15;
    const int ty = tid >> 4;
    const int row0 = blockIdx.x * BM;

    float acc[8][8];
#pragma unroll
    for (int i = 0; i < 8; ++i)
#pragma unroll
        for (int j = 0; j < 8; ++j) acc[i][j] = 0.f;

    for (int kt = 0; kt < FDIM; kt += BK) {
#pragma unroll
        for (int it = 0; it < 2; ++it) {
            int idx = it * 256 + tid;
            int r = idx >> 2;
            int kk = (idx & 3) * 4;
            int grow = row0 + r;
            int k0 = kt + kk;
            float4 v = make_float4(0.f, 0.f, 0.f, 0.f);
            if (grow < NN) {
                v = __ldg((const float4*)&g_h[(size_t)grow * FDIM + k0]);
                v.x = fmaxf(fmaf(v.x, g_scale[k0 + 0], g_shift[k0 + 0]), 0.f);
                v.y = fmaxf(fmaf(v.y, g_scale[k0 + 1], g_shift[k0 + 1]), 0.f);
                v.z = fmaxf(fmaf(v.z, g_scale[k0 + 2], g_shift[k0 + 2]), 0.f);
                v.w = fmaxf(fmaf(v.w, g_scale[k0 + 3], g_shift[k0 + 3]), 0.f);
            }
            a_s[kk + 0][r] = v.x; a_s[kk + 1][r] = v.y;
            a_s[kk + 2][r] = v.z; a_s[kk + 3][r] = v.w;
            int j = r;
            float4 w = __ldg((const float4*)&W2[(size_t)j * FDIM + k0]);
            w_s[kk + 0][j] = w.x; w_s[kk + 1][j] = w.y;
            w_s[kk + 2][j] = w.z; w_s[kk + 3][j] = w.w;
        }
        __syncthreads();
#pragma unroll
        for (int k = 0; k < BK; ++k) {
            float4 a0 = *(const float4*)&a_s[k][ty * 8];
            float4 a1 = *(const float4*)&a_s[k][ty * 8 + 4];
            float4 w0 = *(const float4*)&w_s[k][tx * 8];
            float4 w1 = *(const float4*)&w_s[k][tx * 8 + 4];
            float ar[8] = {a0.x, a0.y, a0.z, a0.w, a1.x, a1.y, a1.z, a1.w};
            float wr[8] = {w0.x, w0.y, w0.z, w0.w, w1.x, w1.y, w1.z, w1.w};
#pragma unroll
            for (int i = 0; i < 8; ++i)
#pragma unroll
                for (int j = 0; j < 8; ++j) acc[i][j] = fmaf(ar[i], wr[j], acc[i][j]);
        }
        __syncthreads();
    }

    float bias[8];
#pragma unroll
    for (int c = 0; c < 8; ++c) bias[c] = __ldg(&b2[tx * 8 + c]);

#pragma unroll
    for (int i = 0; i < 8; ++i) {
        int grow = row0 + ty * 8 + i;
        if (grow < NN) {
            float o[8];
#pragma unroll
            for (int c = 0; c < 8; ++c) o[c] = acc[i][c] + bias[c];
            float4* dst = (float4*)&out[(size_t)grow * FDIM + tx * 8];
            dst[0] = make_float4(o[0], o[1], o[2], o[3]);
            dst[1] = make_float4(o[4], o[5], o[6], o[7]);
        }
    }
}

// ---------------------------------------------------------------------------
extern "C" void kernel_launch(void* const* d_in, const int* in_sizes, int n_in,
                              void* d_out, int out_size) {
    // --- identify inputs by size pattern (robust to metadata ordering) ---
    int idx_x = -1, idx_e = -1, idx_eps = -1;
    int mats[2] = {-1, -1}; int nm = 0;
    int vecs[4] = {-1, -1, -1, -1}; int nv = 0;
    for (int i = 0; i < n_in; ++i) {
        int s = in_sizes[i];
        if (s == NN * FDIM)             idx_x = i;
        else if (s == 1)                idx_eps = i;
        else if (s == FDIM * FDIM)      { if (nm < 2) mats[nm++] = i; }
        else if (s == FDIM)             { if (nv < 4) vecs[nv++] = i; }
        else                            idx_e = i;   // the edge array (2*E elements)
    }

    const float* x     = (const float*)d_in[idx_x];
    const void*  ei    = d_in[idx_e];
    const float* eps   = (const float*)d_in[idx_eps];
    const float* W1    = (const float*)d_in[mats[0]];
    const float* W2    = (const float*)d_in[mats[1]];
    const float *b1, *gamma, *beta, *b2;
    if (idx_x == 0) {          // dict order: x, edge, eps, W1, b1, gamma, beta, W2, b2
        b1    = (const float*)d_in[vecs[0]];
        gamma = (const float*)d_in[vecs[1]];
        beta  = (const float*)d_in[vecs[2]];
        b2    = (const float*)d_in[vecs[3]];
    } else {                   // alphabetical: W1, W2, b1, b2, beta, edge, eps, gamma, x
        b1    = (const float*)d_in[vecs[0]];
        b2    = (const float*)d_in[vecs[1]];
        beta  = (const float*)d_in[vecs[2]];
        gamma = (const float*)d_in[vecs[3]];
    }
    float* out = (float*)d_out;

    const int E = in_sizes[idx_e] / 2;

    detect_kernel<<<1, 32>>>((const long long*)ei);

    const int total4 = NN * FDIM / 4;
    init_kernel<<<(total4 + 255) / 256, 256>>>(x, eps);

    long long sthreads = (long long)E * 32;
    int sblocks = (int)((sthreads + 255) / 256);
    scatter_kernel<<<sblocks, 256>>>(x, ei, E);

    const int gblocks = (NN + BM - 1) / BM;
    gemm1_kernel<<<gblocks, 256>>>(W1, b1);
    finalize_kernel<<<1, FDIM>>>(gamma, beta);
    gemm2_kernel<<<gblocks, 256>>>(W2, b2, out);
}

// round 4
// speedup vs baseline: 1.3780x; 1.3780x over previous
#include <cuda_runtime.h>
#include <cuda_bf16.h>
#include <cstdint>

#define NN 100000
#define FDIM 128
#define BM 128
#define BKK 32
#define SSTRIDE 36   // BKK + 4 -> conflict-free LDS (4*gid+tig) and STS.128

// ---- scratch (device globals: allowed; no runtime allocation) ----
__device__ float g_agg[(size_t)NN * FDIM];   // (1+eps)*x + neighbor_sum
__device__ float g_h[(size_t)NN * FDIM];     // h after GEMM1 (+b1)
__device__ float g_sum[FDIM];
__device__ float g_sq[FDIM];
__device__ float g_scale[FDIM];
__device__ float g_shift[FDIM];
__device__ int   g_ei64;                     // 1 if edge_index is int64, 0 if int32

// ---------------------------------------------------------------------------
__device__ __forceinline__ uint32_t f2tf32(float f) {
    uint32_t u;
    asm("cvt.rna.tf32.f32 %0, %1;" : "=r"(u) : "f"(f));
    return u;
}

__device__ __forceinline__ void mma_tf32(float c[4],
                                         uint32_t a0, uint32_t a1, uint32_t a2, uint32_t a3,
                                         uint32_t b0, uint32_t b1) {
    asm volatile(
        "mma.sync.aligned.m16n8k8.row.col.f32.tf32.tf32.f32 "
        "{%0,%1,%2,%3}, {%4,%5,%6,%7}, {%8,%9}, {%0,%1,%2,%3};"
        : "+f"(c[0]), "+f"(c[1]), "+f"(c[2]), "+f"(c[3])
        : "r"(a0), "r"(a1), "r"(a2), "r"(a3), "r"(b0), "r"(b1));
}

// ---------------------------------------------------------------------------
// Kernel 0: probe edge_index dtype. int64 data always lies in [0, NN);
// int32 data read as int64 fuses two indices -> value >= 2^32 w.h.p.
// ---------------------------------------------------------------------------
__global__ void detect_kernel(const long long* __restrict__ ei) {
    if (threadIdx.x == 0) {
        int ok64 = 1;
        for (int i = 0; i < 64; ++i) {
            long long v = ei[i];
            if (v < 0 || v >= NN) { ok64 = 0; break; }
        }
        g_ei64 = ok64;
    }
}

// ---------------------------------------------------------------------------
// Kernel 1: agg = (1+eps)*x ; zero BN stat accumulators
// ---------------------------------------------------------------------------
__global__ __launch_bounds__(256) void init_kernel(const float* __restrict__ x,
                                                   const float* __restrict__ eps) {
    int i = blockIdx.x * 256 + threadIdx.x;
    if (i < FDIM) { g_sum[i] = 0.f; g_sq[i] = 0.f; }
    const int total4 = NN * FDIM / 4;
    if (i < total4) {
        float c = 1.0f + __ldg(eps);
        float4 v = __ldg(((const float4*)x) + i);
        v.x *= c; v.y *= c; v.z *= c; v.w *= c;
        ((float4*)g_agg)[i] = v;
    }
}

// ---------------------------------------------------------------------------
// Kernel 2: scatter-add neighbor features. One warp per edge, float4/lane.
// ---------------------------------------------------------------------------
__global__ __launch_bounds__(256) void scatter_kernel(const float* __restrict__ x,
                                                      const void* __restrict__ ei_raw,
                                                      int E) {
    int gtid = blockIdx.x * 256 + threadIdx.x;
    int e = gtid >> 5;
    int lane = gtid & 31;
    if (e >= E) return;
    long long r, c;
    if (g_ei64) {
        const long long* ei = (const long long*)ei_raw;
        r = __ldg(&ei[e]);
        c = __ldg(&ei[E + e]);
    } else {
        const int* ei = (const int*)ei_raw;
        r = __ldg(&ei[e]);
        c = __ldg(&ei[E + e]);
    }
    if ((unsigned long long)r >= NN || (unsigned long long)c >= NN) return;
    float4 v = __ldg(((const float4*)(x + c * FDIM)) + lane);
    float* dst = g_agg + r * FDIM + lane * 4;
    asm volatile("red.global.add.v4.f32 [%0], {%1, %2, %3, %4};"
                 :: "l"(dst), "f"(v.x), "f"(v.y), "f"(v.z), "f"(v.w) : "memory");
}

// ---------------------------------------------------------------------------
// Kernel 3: GEMM1 (tf32 tensor cores)  h = agg @ W1^T + b1, fused BN stats.
// Block: 128x128 tile, 8 warps as 4(M) x 2(N); warp tile 32x64.
// mma.m16n8k8: per warp 2 m-tiles x 8 n-tiles.
// ---------------------------------------------------------------------------
__global__ __launch_bounds__(256) void gemm1_kernel(const float* __restrict__ W1,
                                                    const float* __restrict__ b1) {
    __shared__ uint32_t s_a[BM][SSTRIDE];
    __shared__ uint32_t s_w[FDIM][SSTRIDE];
    __shared__ float sh_sum[FDIM];
    __shared__ float sh_sq[FDIM];

    const int tid  = threadIdx.x;
    const int lane = tid & 31;
    const int wid  = tid >> 5;
    const int wm   = wid >> 1;            // 0..3
    const int wn   = wid & 1;             // 0..1
    const int gid  = lane >> 2;           // 0..7
    const int tig  = lane & 3;            // 0..3
    const int row0 = blockIdx.x * BM;

    if (tid < FDIM) { sh_sum[tid] = 0.f; sh_sq[tid] = 0.f; }

    float c[2][8][4];
#pragma unroll
    for (int mt = 0; mt < 2; ++mt)
#pragma unroll
        for (int nt = 0; nt < 8; ++nt)
#pragma unroll
            for (int j = 0; j < 4; ++j) c[mt][nt][j] = 0.f;

    for (int kt = 0; kt < FDIM; kt += BKK) {
        if (kt) __syncthreads();
#pragma unroll
        for (int it = 0; it < 4; ++it) {
            int idx = it * 256 + tid;       // 0..1023
            int r   = idx >> 3;             // 0..127
            int kk  = (idx & 7) * 4;        // 0..28
            int grow = row0 + r;
            float4 v = make_float4(0.f, 0.f, 0.f, 0.f);
            if (grow < NN) v = __ldg((const float4*)&g_agg[(size_t)grow * FDIM + kt + kk]);
            uint4 u;
            u.x = f2tf32(v.x); u.y = f2tf32(v.y); u.z = f2tf32(v.z); u.w = f2tf32(v.w);
            *(uint4*)&s_a[r][kk] = u;
            float4 w = __ldg((const float4*)&W1[(size_t)r * FDIM + kt + kk]);
            uint4 uw;
            uw.x = f2tf32(w.x); uw.y = f2tf32(w.y); uw.z = f2tf32(w.z); uw.w = f2tf32(w.w);
            *(uint4*)&s_w[r][kk] = uw;
        }
        __syncthreads();

#pragma unroll
        for (int ks = 0; ks < 4; ++ks) {
            int k0 = ks * 8;
            uint32_t af[2][4];
#pragma unroll
            for (int mt = 0; mt < 2; ++mt) {
                int rb = wm * 32 + mt * 16 + gid;
                af[mt][0] = s_a[rb][k0 + tig];
                af[mt][1] = s_a[rb + 8][k0 + tig];
                af[mt][2] = s_a[rb][k0 + tig + 4];
                af[mt][3] = s_a[rb + 8][k0 + tig + 4];
            }
#pragma unroll
            for (int nt = 0; nt < 8; ++nt) {
                int nb = wn * 64 + nt * 8 + gid;
                uint32_t bb0 = s_w[nb][k0 + tig];
                uint32_t bb1 = s_w[nb][k0 + tig + 4];
                mma_tf32(c[0][nt], af[0][0], af[0][1], af[0][2], af[0][3], bb0, bb1);
                mma_tf32(c[1][nt], af[1][0], af[1][1], af[1][2], af[1][3], bb0, bb1);
            }
        }
    }
    __syncthreads();

    // epilogue: bias, store h, accumulate BN stats
    float psum[8][2], psq[8][2];
#pragma unroll
    for (int nt = 0; nt < 8; ++nt) {
        psum[nt][0] = 0.f; psum[nt][1] = 0.f;
        psq[nt][0] = 0.f;  psq[nt][1] = 0.f;
    }

#pragma unroll
    for (int nt = 0; nt < 8; ++nt) {
        int col = wn * 64 + nt * 8 + 2 * tig;
        float2 bb = __ldg((const float2*)&b1[col]);
#pragma unroll
        for (int mt = 0; mt < 2; ++mt) {
            int r0g = row0 + wm * 32 + mt * 16 + gid;
            if (r0g < NN) {
                float h0 = c[mt][nt][0] + bb.x;
                float h1 = c[mt][nt][1] + bb.y;
                *(float2*)&g_h[(size_t)r0g * FDIM + col] = make_float2(h0, h1);
                psum[nt][0] += h0; psum[nt][1] += h1;
                psq[nt][0] += h0 * h0; psq[nt][1] += h1 * h1;
            }
            int r1g = r0g + 8;
            if (r1g < NN) {
                float h0 = c[mt][nt][2] + bb.x;
                float h1 = c[mt][nt][3] + bb.y;
                *(float2*)&g_h[(size_t)r1g * FDIM + col] = make_float2(h0, h1);
                psum[nt][0] += h0; psum[nt][1] += h1;
                psq[nt][0] += h0 * h0; psq[nt][1] += h1 * h1;
            }
        }
    }

    // reduce across the 8 row-lanes (gid); keeps tig structure intact
#pragma unroll
    for (int off = 16; off >= 4; off >>= 1) {
#pragma unroll
        for (int nt = 0; nt < 8; ++nt) {
#pragma unroll
            for (int j = 0; j < 2; ++j) {
                psum[nt][j] += __shfl_xor_sync(0xffffffffu, psum[nt][j], off);
                psq[nt][j]  += __shfl_xor_sync(0xffffffffu, psq[nt][j], off);
            }
        }
    }
    if (gid == 0) {
#pragma unroll
        for (int nt = 0; nt < 8; ++nt) {
            int col = wn * 64 + nt * 8 + 2 * tig;
            atomicAdd(&sh_sum[col],     psum[nt][0]);
            atomicAdd(&sh_sum[col + 1], psum[nt][1]);
            atomicAdd(&sh_sq[col],      psq[nt][0]);
            atomicAdd(&sh_sq[col + 1],  psq[nt][1]);
        }
    }
    __syncthreads();
    if (tid < FDIM) {
        atomicAdd(&g_sum[tid], sh_sum[tid]);
        atomicAdd(&g_sq[tid],  sh_sq[tid]);
    }
}

// ---------------------------------------------------------------------------
// Kernel 4: fold BN into scale/shift
// ---------------------------------------------------------------------------
__global__ void finalize_kernel(const float* __restrict__ gamma,
                                const float* __restrict__ beta) {
    int i = threadIdx.x;
    float invn = 1.0f / (float)NN;
    float mean = g_sum[i] * invn;
    float var = g_sq[i] * invn - mean * mean;
    float rstd = rsqrtf(var + 1e-5f);
    float sc = rstd * __ldg(&gamma[i]);
    g_scale[i] = sc;
    g_shift[i] = __ldg(&beta[i]) - mean * sc;
}

// ---------------------------------------------------------------------------
// Kernel 5: GEMM2 (tf32 tensor cores)  out = relu(h*scale+shift) @ W2^T + b2
// ---------------------------------------------------------------------------
__global__ __launch_bounds__(256) void gemm2_kernel(const float* __restrict__ W2,
                                                    const float* __restrict__ b2,
                                                    float* __restrict__ out) {
    __shared__ uint32_t s_a[BM][SSTRIDE];
    __shared__ uint32_t s_w[FDIM][SSTRIDE];

    const int tid  = threadIdx.x;
    const int lane = tid & 31;
    const int wid  = tid >> 5;
    const int wm   = wid >> 1;
    const int wn   = wid & 1;
    const int gid  = lane >> 2;
    const int tig  = lane & 3;
    const int row0 = blockIdx.x * BM;

    float c[2][8][4];
#pragma unroll
    for (int mt = 0; mt < 2; ++mt)
#pragma unroll
        for (int nt = 0; nt < 8; ++nt)
#pragma unroll
            for (int j = 0; j < 4; ++j) c[mt][nt][j] = 0.f;

    for (int kt = 0; kt < FDIM; kt += BKK) {
        if (kt) __syncthreads();
#pragma unroll
        for (int it = 0; it < 4; ++it) {
            int idx = it * 256 + tid;
            int r   = idx >> 3;
            int kk  = (idx & 7) * 4;
            int k0  = kt + kk;
            int grow = row0 + r;
            float4 v = make_float4(0.f, 0.f, 0.f, 0.f);
            if (grow < NN) {
                v = __ldg((const float4*)&g_h[(size_t)grow * FDIM + k0]);
                float4 sc = *(const float4*)&g_scale[k0];
                float4 sh = *(const float4*)&g_shift[k0];
                v.x = fmaxf(fmaf(v.x, sc.x, sh.x), 0.f);
                v.y = fmaxf(fmaf(v.y, sc.y, sh.y), 0.f);
                v.z = fmaxf(fmaf(v.z, sc.z, sh.z), 0.f);
                v.w = fmaxf(fmaf(v.w, sc.w, sh.w), 0.f);
            }
            uint4 u;
            u.x = f2tf32(v.x); u.y = f2tf32(v.y); u.z = f2tf32(v.z); u.w = f2tf32(v.w);
            *(uint4*)&s_a[r][kk] = u;
            float4 w = __ldg((const float4*)&W2[(size_t)r * FDIM + k0]);
            uint4 uw;
            uw.x = f2tf32(w.x); uw.y = f2tf32(w.y); uw.z = f2tf32(w.z); uw.w = f2tf32(w.w);
            *(uint4*)&s_w[r][kk] = uw;
        }
        __syncthreads();

#pragma unroll
        for (int ks = 0; ks < 4; ++ks) {
            int k0 = ks * 8;
            uint32_t af[2][4];
#pragma unroll
            for (int mt = 0; mt < 2; ++mt) {
                int rb = wm * 32 + mt * 16 + gid;
                af[mt][0] = s_a[rb][k0 + tig];
                af[mt][1] = s_a[rb + 8][k0 + tig];
                af[mt][2] = s_a[rb][k0 + tig + 4];
                af[mt][3] = s_a[rb + 8][k0 + tig + 4];
            }
#pragma unroll
            for (int nt = 0; nt < 8; ++nt) {
                int nb = wn * 64 + nt * 8 + gid;
                uint32_t bb0 = s_w[nb][k0 + tig];
                uint32_t bb1 = s_w[nb][k0 + tig + 4];
                mma_tf32(c[0][nt], af[0][0], af[0][1], af[0][2], af[0][3], bb0, bb1);
                mma_tf32(c[1][nt], af[1][0], af[1][1], af[1][2], af[1][3], bb0, bb1);
            }
        }
    }

#pragma unroll
    for (int nt = 0; nt < 8; ++nt) {
        int col = wn * 64 + nt * 8 + 2 * tig;
        float2 bb = __ldg((const float2*)&b2[col]);
#pragma unroll
        for (int mt = 0; mt < 2; ++mt) {
            int r0g = row0 + wm * 32 + mt * 16 + gid;
            if (r0g < NN) {
                *(float2*)&out[(size_t)r0g * FDIM + col] =
                    make_float2(c[mt][nt][0] + bb.x, c[mt][nt][1] + bb.y);
            }
            int r1g = r0g + 8;
            if (r1g < NN) {
                *(float2*)&out[(size_t)r1g * FDIM + col] =
                    make_float2(c[mt][nt][2] + bb.x, c[mt][nt][3] + bb.y);
            }
        }
    }
}

// ---------------------------------------------------------------------------
extern "C" void kernel_launch(void* const* d_in, const int* in_sizes, int n_in,
                              void* d_out, int out_size) {
    // --- identify inputs by size pattern (robust to metadata ordering) ---
    int idx_x = -1, idx_e = -1, idx_eps = -1;
    int mats[2] = {-1, -1}; int nm = 0;
    int vecs[4] = {-1, -1, -1, -1}; int nv = 0;
    for (int i = 0; i < n_in; ++i) {
        int s = in_sizes[i];
        if (s == NN * FDIM)             idx_x = i;
        else if (s == 1)                idx_eps = i;
        else if (s == FDIM * FDIM)      { if (nm < 2) mats[nm++] = i; }
        else if (s == FDIM)             { if (nv < 4) vecs[nv++] = i; }
        else                            idx_e = i;   // the edge array (2*E elements)
    }

    const float* x     = (const float*)d_in[idx_x];
    const void*  ei    = d_in[idx_e];
    const float* eps   = (const float*)d_in[idx_eps];
    const float* W1    = (const float*)d_in[mats[0]];
    const float* W2    = (const float*)d_in[mats[1]];
    const float *b1, *gamma, *beta, *b2;
    if (idx_x == 0) {          // dict order: x, edge, eps, W1, b1, gamma, beta, W2, b2
        b1    = (const float*)d_in[vecs[0]];
        gamma = (const float*)d_in[vecs[1]];
        beta  = (const float*)d_in[vecs[2]];
        b2    = (const float*)d_in[vecs[3]];
    } else {                   // alphabetical: W1, W2, b1, b2, beta, edge, eps, gamma, x
        b1    = (const float*)d_in[vecs[0]];
        b2    = (const float*)d_in[vecs[1]];
        beta  = (const float*)d_in[vecs[2]];
        gamma = (const float*)d_in[vecs[3]];
    }
    float* out = (float*)d_out;

    const int E = in_sizes[idx_e] / 2;

    detect_kernel<<<1, 32>>>((const long long*)ei);

    const int total4 = NN * FDIM / 4;
    init_kernel<<<(total4 + 255) / 256, 256>>>(x, eps);

    long long sthreads = (long long)E * 32;
    int sblocks = (int)((sthreads + 255) / 256);
    scatter_kernel<<<sblocks, 256>>>(x, ei, E);

    const int gblocks = (NN + BM - 1) / BM;
    gemm1_kernel<<<gblocks, 256>>>(W1, b1);
    finalize_kernel<<<1, FDIM>>>(gamma, beta);
    gemm2_kernel<<<gblocks, 256>>>(W2, b2, out);
}

// round 6
// speedup vs baseline: 2.2545x; 1.6361x over previous
#include <cuda_runtime.h>
#include <cuda_bf16.h>
#include <cstdint>

#define NN 100000
#define FDIM 128
#define BM 128
#define BKK 32
#define SSTRIDE 36   // BKK + 4 -> conflict-free LDS (4*gid+tig) and STS.128
#define EMAX 1600000
#define SCAN_B 1024
#define NBLK ((NN + SCAN_B - 1) / SCAN_B)   // 98

// ---- scratch (device globals: allowed; no runtime allocation) ----
__device__ float g_agg[(size_t)NN * FDIM];   // (1+eps)*x + neighbor_sum
__device__ float g_h[(size_t)NN * FDIM];     // h after GEMM1 (+b1)
__device__ float g_sum[FDIM];
__device__ float g_sq[FDIM];
__device__ float g_scale[FDIM];
__device__ float g_shift[FDIM];
__device__ int   g_ei64;                     // 1 if edge_index is int64, 0 if int32
__device__ int   g_cnt[NN];                  // counts -> cursor
__device__ int   g_rowptr[NN + 1];           // pristine CSR offsets
__device__ int   g_bsum[NBLK];
__device__ int   g_boff[NBLK];
__device__ int   g_src[EMAX];                // sources sorted by destination

// ---------------------------------------------------------------------------
__device__ __forceinline__ uint32_t f2tf32(float f) {
    uint32_t u;
    asm("cvt.rna.tf32.f32 %0, %1;" : "=r"(u) : "f"(f));
    return u;
}

__device__ __forceinline__ void mma_tf32(float c[4],
                                         uint32_t a0, uint32_t a1, uint32_t a2, uint32_t a3,
                                         uint32_t b0, uint32_t b1) {
    asm volatile(
        "mma.sync.aligned.m16n8k8.row.col.f32.tf32.tf32.f32 "
        "{%0,%1,%2,%3}, {%4,%5,%6,%7}, {%8,%9}, {%0,%1,%2,%3};"
        : "+f"(c[0]), "+f"(c[1]), "+f"(c[2]), "+f"(c[3])
        : "r"(a0), "r"(a1), "r"(a2), "r"(a3), "r"(b0), "r"(b1));
}

__device__ __forceinline__ int edge_at(const void* ei_raw, long long pos) {
    if (g_ei64) return (int)__ldg(((const long long*)ei_raw) + pos);
    return __ldg(((const int*)ei_raw) + pos);
}

// ---------------------------------------------------------------------------
// Kernel 0: probe edge_index dtype (int64 values always in [0, NN)).
// ---------------------------------------------------------------------------
__global__ void detect_kernel(const long long* __restrict__ ei) {
    if (threadIdx.x == 0) {
        int ok64 = 1;
        for (int i = 0; i < 64; ++i) {
            long long v = ei[i];
            if (v < 0 || v >= NN) { ok64 = 0; break; }
        }
        g_ei64 = ok64;
    }
}

// ---------------------------------------------------------------------------
// CSR build phase
// ---------------------------------------------------------------------------
__global__ __launch_bounds__(256) void zero_cnt_kernel() {
    int i = blockIdx.x * 256 + threadIdx.x;
    if (i < NN) g_cnt[i] = 0;
}

__global__ __launch_bounds__(256) void hist_kernel(const void* __restrict__ ei, int E) {
    int e = blockIdx.x * 256 + threadIdx.x;
    if (e >= E) return;
    int r = edge_at(ei, e);
    if ((unsigned)r < NN) atomicAdd(&g_cnt[r], 1);
}

// block-level sums of counts
__global__ __launch_bounds__(SCAN_B) void bsum_kernel() {
    __shared__ int sm[32];
    int tid = threadIdx.x, lane = tid & 31, wid = tid >> 5;
    int i = blockIdx.x * SCAN_B + tid;
    int v = (i < NN) ? g_cnt[i] : 0;
#pragma unroll
    for (int o = 16; o; o >>= 1) v += __shfl_xor_sync(~0u, v, o);
    if (lane == 0) sm[wid] = v;
    __syncthreads();
    if (wid == 0) {
        int w = sm[lane];
#pragma unroll
        for (int o = 16; o; o >>= 1) w += __shfl_xor_sync(~0u, w, o);
        if (lane == 0) g_bsum[blockIdx.x] = w;
    }
}

// scan block sums (1 block); also zero BN accumulators
__global__ __launch_bounds__(128) void bscan_kernel() {
    int tid = threadIdx.x;
    if (tid < FDIM) { g_sum[tid] = 0.f; g_sq[tid] = 0.f; }
    if (tid == 0) {
        int run = 0;
        for (int b = 0; b < NBLK; ++b) { g_boff[b] = run; run += g_bsum[b]; }
        g_rowptr[NN] = run;
    }
}

// per-element exclusive scan + block offset -> rowptr + cursor
__global__ __launch_bounds__(SCAN_B) void scan2_kernel() {
    __shared__ int wsum[32];
    int tid = threadIdx.x, lane = tid & 31, wid = tid >> 5;
    int i = blockIdx.x * SCAN_B + tid;
    int v = (i < NN) ? g_cnt[i] : 0;
    int incl = v;
#pragma unroll
    for (int o = 1; o < 32; o <<= 1) {
        int t = __shfl_up_sync(~0u, incl, o);
        if (lane >= o) incl += t;
    }
    if (lane == 31) wsum[wid] = incl;
    __syncthreads();
    if (wid == 0) {
        int wv = wsum[lane];
        int winc = wv;
#pragma unroll
        for (int o = 1; o < 32; o <<= 1) {
            int t = __shfl_up_sync(~0u, winc, o);
            if (lane >= o) winc += t;
        }
        wsum[lane] = winc - wv;
    }
    __syncthreads();
    if (i < NN) {
        int excl = incl - v + wsum[wid] + g_boff[blockIdx.x];
        g_rowptr[i] = excl;
        g_cnt[i] = excl;          // cursor for reorder
    }
}

__global__ __launch_bounds__(256) void reorder_kernel(const void* __restrict__ ei, int E) {
    int e = blockIdx.x * 256 + threadIdx.x;
    if (e >= E) return;
    int r = edge_at(ei, e);
    int c = edge_at(ei, (long long)E + e);
    if ((unsigned)r >= NN || (unsigned)c >= NN) return;
    int pos = atomicAdd(&g_cnt[r], 1);
    if ((unsigned)pos < EMAX) g_src[pos] = c;
}

// ---------------------------------------------------------------------------
// Gather-accumulate: one warp per destination node.
// agg[n] = (1+eps)*x[n] + sum_{s in nbrs(n)} x[s]
// ---------------------------------------------------------------------------
__global__ __launch_bounds__(256) void gather_kernel(const float* __restrict__ x,
                                                     const float* __restrict__ eps) {
    int gw = (blockIdx.x * 256 + threadIdx.x) >> 5;
    int lane = threadIdx.x & 31;
    if (gw >= NN) return;
    int beg = __ldg(&g_rowptr[gw]);
    int end = __ldg(&g_rowptr[gw + 1]);
    float cc = 1.0f + __ldg(eps);
    float4 v = __ldg(((const float4*)(x + (size_t)gw * FDIM)) + lane);
    float4 acc = make_float4(v.x * cc, v.y * cc, v.z * cc, v.w * cc);
    int j = beg;
    for (; j + 2 <= end; j += 2) {
        int s0 = __ldg(&g_src[j]);
        int s1 = __ldg(&g_src[j + 1]);
        float4 a = __ldg(((const float4*)(x + (size_t)s0 * FDIM)) + lane);
        float4 b = __ldg(((const float4*)(x + (size_t)s1 * FDIM)) + lane);
        acc.x += a.x + b.x; acc.y += a.y + b.y;
        acc.z += a.z + b.z; acc.w += a.w + b.w;
    }
    if (j < end) {
        int s0 = __ldg(&g_src[j]);
        float4 a = __ldg(((const float4*)(x + (size_t)s0 * FDIM)) + lane);
        acc.x += a.x; acc.y += a.y; acc.z += a.z; acc.w += a.w;
    }
    ((float4*)(g_agg + (size_t)gw * FDIM))[lane] = acc;
}

// ---------------------------------------------------------------------------
// Kernel 3: GEMM1 (tf32)  h = agg @ W1^T + b1, fused BN stats.
// ---------------------------------------------------------------------------
__global__ __launch_bounds__(256) void gemm1_kernel(const float* __restrict__ W1,
                                                    const float* __restrict__ b1) {
    __shared__ uint32_t s_a[BM][SSTRIDE];
    __shared__ uint32_t s_w[FDIM][SSTRIDE];
    __shared__ float sh_sum[FDIM];
    __shared__ float sh_sq[FDIM];

    const int tid  = threadIdx.x;
    const int lane = tid & 31;
    const int wid  = tid >> 5;
    const int wm   = wid >> 1;
    const int wn   = wid & 1;
    const int gid  = lane >> 2;
    const int tig  = lane & 3;
    const int row0 = blockIdx.x * BM;

    if (tid < FDIM) { sh_sum[tid] = 0.f; sh_sq[tid] = 0.f; }

    float c[2][8][4];
#pragma unroll
    for (int mt = 0; mt < 2; ++mt)
#pragma unroll
        for (int nt = 0; nt < 8; ++nt)
#pragma unroll
            for (int j = 0; j < 4; ++j) c[mt][nt][j] = 0.f;

    for (int kt = 0; kt < FDIM; kt += BKK) {
        if (kt) __syncthreads();
#pragma unroll
        for (int it = 0; it < 4; ++it) {
            int idx = it * 256 + tid;
            int r   = idx >> 3;
            int kk  = (idx & 7) * 4;
            int grow = row0 + r;
            float4 v = make_float4(0.f, 0.f, 0.f, 0.f);
            if (grow < NN) v = __ldg((const float4*)&g_agg[(size_t)grow * FDIM + kt + kk]);
            uint4 u;
            u.x = f2tf32(v.x); u.y = f2tf32(v.y); u.z = f2tf32(v.z); u.w = f2tf32(v.w);
            *(uint4*)&s_a[r][kk] = u;
            float4 w = __ldg((const float4*)&W1[(size_t)r * FDIM + kt + kk]);
            uint4 uw;
            uw.x = f2tf32(w.x); uw.y = f2tf32(w.y); uw.z = f2tf32(w.z); uw.w = f2tf32(w.w);
            *(uint4*)&s_w[r][kk] = uw;
        }
        __syncthreads();

#pragma unroll
        for (int ks = 0; ks < 4; ++ks) {
            int k0 = ks * 8;
            uint32_t af[2][4];
#pragma unroll
            for (int mt = 0; mt < 2; ++mt) {
                int rb = wm * 32 + mt * 16 + gid;
                af[mt][0] = s_a[rb][k0 + tig];
                af[mt][1] = s_a[rb + 8][k0 + tig];
                af[mt][2] = s_a[rb][k0 + tig + 4];
                af[mt][3] = s_a[rb + 8][k0 + tig + 4];
            }
#pragma unroll
            for (int nt = 0; nt < 8; ++nt) {
                int nb = wn * 64 + nt * 8 + gid;
                uint32_t bb0 = s_w[nb][k0 + tig];
                uint32_t bb1 = s_w[nb][k0 + tig + 4];
                mma_tf32(c[0][nt], af[0][0], af[0][1], af[0][2], af[0][3], bb0, bb1);
                mma_tf32(c[1][nt], af[1][0], af[1][1], af[1][2], af[1][3], bb0, bb1);
            }
        }
    }
    __syncthreads();

    float psum[8][2], psq[8][2];
#pragma unroll
    for (int nt = 0; nt < 8; ++nt) {
        psum[nt][0] = 0.f; psum[nt][1] = 0.f;
        psq[nt][0] = 0.f;  psq[nt][1] = 0.f;
    }

#pragma unroll
    for (int nt = 0; nt < 8; ++nt) {
        int col = wn * 64 + nt * 8 + 2 * tig;
        float2 bb = __ldg((const float2*)&b1[col]);
#pragma unroll
        for (int mt = 0; mt < 2; ++mt) {
            int r0g = row0 + wm * 32 + mt * 16 + gid;
            if (r0g < NN) {
                float h0 = c[mt][nt][0] + bb.x;
                float h1 = c[mt][nt][1] + bb.y;
                *(float2*)&g_h[(size_t)r0g * FDIM + col] = make_float2(h0, h1);
                psum[nt][0] += h0; psum[nt][1] += h1;
                psq[nt][0] += h0 * h0; psq[nt][1] += h1 * h1;
            }
            int r1g = r0g + 8;
            if (r1g < NN) {
                float h0 = c[mt][nt][2] + bb.x;
                float h1 = c[mt][nt][3] + bb.y;
                *(float2*)&g_h[(size_t)r1g * FDIM + col] = make_float2(h0, h1);
                psum[nt][0] += h0; psum[nt][1] += h1;
                psq[nt][0] += h0 * h0; psq[nt][1] += h1 * h1;
            }
        }
    }

#pragma unroll
    for (int off = 16; off >= 4; off >>= 1) {
#pragma unroll
        for (int nt = 0; nt < 8; ++nt) {
#pragma unroll
            for (int j = 0; j < 2; ++j) {
                psum[nt][j] += __shfl_xor_sync(0xffffffffu, psum[nt][j], off);
                psq[nt][j]  += __shfl_xor_sync(0xffffffffu, psq[nt][j], off);
            }
        }
    }
    if (gid == 0) {
#pragma unroll
        for (int nt = 0; nt < 8; ++nt) {
            int col = wn * 64 + nt * 8 + 2 * tig;
            atomicAdd(&sh_sum[col],     psum[nt][0]);
            atomicAdd(&sh_sum[col + 1], psum[nt][1]);
            atomicAdd(&sh_sq[col],      psq[nt][0]);
            atomicAdd(&sh_sq[col + 1],  psq[nt][1]);
        }
    }
    __syncthreads();
    if (tid < FDIM) {
        atomicAdd(&g_sum[tid], sh_sum[tid]);
        atomicAdd(&g_sq[tid],  sh_sq[tid]);
    }
}

// ---------------------------------------------------------------------------
__global__ void finalize_kernel(const float* __restrict__ gamma,
                                const float* __restrict__ beta) {
    int i = threadIdx.x;
    float invn = 1.0f / (float)NN;
    float mean = g_sum[i] * invn;
    float var = g_sq[i] * invn - mean * mean;
    float rstd = rsqrtf(var + 1e-5f);
    float sc = rstd * __ldg(&gamma[i]);
    g_scale[i] = sc;
    g_shift[i] = __ldg(&beta[i]) - mean * sc;
}

// ---------------------------------------------------------------------------
// Kernel 5: GEMM2 (tf32)  out = relu(h*scale+shift) @ W2^T + b2
// ---------------------------------------------------------------------------
__global__ __launch_bounds__(256) void gemm2_kernel(const float* __restrict__ W2,
                                                    const float* __restrict__ b2,
                                                    float* __restrict__ out) {
    __shared__ uint32_t s_a[BM][SSTRIDE];
    __shared__ uint32_t s_w[FDIM][SSTRIDE];

    const int tid  = threadIdx.x;
    const int lane = tid & 31;
    const int wid  = tid >> 5;
    const int wm   = wid >> 1;
    const int wn   = wid & 1;
    const int gid  = lane >> 2;
    const int tig  = lane & 3;
    const int row0 = blockIdx.x * BM;

    float c[2][8][4];
#pragma unroll
    for (int mt = 0; mt < 2; ++mt)
#pragma unroll
        for (int nt = 0; nt < 8; ++nt)
#pragma unroll
            for (int j = 0; j < 4; ++j) c[mt][nt][j] = 0.f;

    for (int kt = 0; kt < FDIM; kt += BKK) {
        if (kt) __syncthreads();
#pragma unroll
        for (int it = 0; it < 4; ++it) {
            int idx = it * 256 + tid;
            int r   = idx >> 3;
            int kk  = (idx & 7) * 4;
            int k0  = kt + kk;
            int grow = row0 + r;
            float4 v = make_float4(0.f, 0.f, 0.f, 0.f);
            if (grow < NN) {
                v = __ldg((const float4*)&g_h[(size_t)grow * FDIM + k0]);
                float4 sc = *(const float4*)&g_scale[k0];
                float4 sh = *(const float4*)&g_shift[k0];
                v.x = fmaxf(fmaf(v.x, sc.x, sh.x), 0.f);
                v.y = fmaxf(fmaf(v.y, sc.y, sh.y), 0.f);
                v.z = fmaxf(fmaf(v.z, sc.z, sh.z), 0.f);
                v.w = fmaxf(fmaf(v.w, sc.w, sh.w), 0.f);
            }
            uint4 u;
            u.x = f2tf32(v.x); u.y = f2tf32(v.y); u.z = f2tf32(v.z); u.w = f2tf32(v.w);
            *(uint4*)&s_a[r][kk] = u;
            float4 w = __ldg((const float4*)&W2[(size_t)r * FDIM + k0]);
            uint4 uw;
            uw.x = f2tf32(w.x); uw.y = f2tf32(w.y); uw.z = f2tf32(w.z); uw.w = f2tf32(w.w);
            *(uint4*)&s_w[r][kk] = uw;
        }
        __syncthreads();

#pragma unroll
        for (int ks = 0; ks < 4; ++ks) {
            int k0 = ks * 8;
            uint32_t af[2][4];
#pragma unroll
            for (int mt = 0; mt < 2; ++mt) {
                int rb = wm * 32 + mt * 16 + gid;
                af[mt][0] = s_a[rb][k0 + tig];
                af[mt][1] = s_a[rb + 8][k0 + tig];
                af[mt][2] = s_a[rb][k0 + tig + 4];
                af[mt][3] = s_a[rb + 8][k0 + tig + 4];
            }
#pragma unroll
            for (int nt = 0; nt < 8; ++nt) {
                int nb = wn * 64 + nt * 8 + gid;
                uint32_t bb0 = s_w[nb][k0 + tig];
                uint32_t bb1 = s_w[nb][k0 + tig + 4];
                mma_tf32(c[0][nt], af[0][0], af[0][1], af[0][2], af[0][3], bb0, bb1);
                mma_tf32(c[1][nt], af[1][0], af[1][1], af[1][2], af[1][3], bb0, bb1);
            }
        }
    }

#pragma unroll
    for (int nt = 0; nt < 8; ++nt) {
        int col = wn * 64 + nt * 8 + 2 * tig;
        float2 bb = __ldg((const float2*)&b2[col]);
#pragma unroll
        for (int mt = 0; mt < 2; ++mt) {
            int r0g = row0 + wm * 32 + mt * 16 + gid;
            if (r0g < NN) {
                *(float2*)&out[(size_t)r0g * FDIM + col] =
                    make_float2(c[mt][nt][0] + bb.x, c[mt][nt][1] + bb.y);
            }
            int r1g = r0g + 8;
            if (r1g < NN) {
                *(float2*)&out[(size_t)r1g * FDIM + col] =
                    make_float2(c[mt][nt][2] + bb.x, c[mt][nt][3] + bb.y);
            }
        }
    }
}

// ---------------------------------------------------------------------------
extern "C" void kernel_launch(void* const* d_in, const int* in_sizes, int n_in,
                              void* d_out, int out_size) {
    // --- identify inputs by size pattern (robust to metadata ordering) ---
    int idx_x = -1, idx_e = -1, idx_eps = -1;
    int mats[2] = {-1, -1}; int nm = 0;
    int vecs[4] = {-1, -1, -1, -1}; int nv = 0;
    for (int i = 0; i < n_in; ++i) {
        int s = in_sizes[i];
        if (s == NN * FDIM)             idx_x = i;
        else if (s == 1)                idx_eps = i;
        else if (s == FDIM * FDIM)      { if (nm < 2) mats[nm++] = i; }
        else if (s == FDIM)             { if (nv < 4) vecs[nv++] = i; }
        else                            idx_e = i;
    }

    const float* x     = (const float*)d_in[idx_x];
    const void*  ei    = d_in[idx_e];
    const float* eps   = (const float*)d_in[idx_eps];
    const float* W1    = (const float*)d_in[mats[0]];
    const float* W2    = (const float*)d_in[mats[1]];
    const float *b1, *gamma, *beta, *b2;
    if (idx_x == 0) {          // dict order: x, edge, eps, W1, b1, gamma, beta, W2, b2
        b1    = (const float*)d_in[vecs[0]];
        gamma = (const float*)d_in[vecs[1]];
        beta  = (const float*)d_in[vecs[2]];
        b2    = (const float*)d_in[vecs[3]];
    } else {                   // alphabetical: W1, W2, b1, b2, beta, edge, eps, gamma, x
        b1    = (const float*)d_in[vecs[0]];
        b2    = (const float*)d_in[vecs[1]];
        beta  = (const float*)d_in[vecs[2]];
        gamma = (const float*)d_in[vecs[3]];
    }
    float* out = (float*)d_out;

    const int E = in_sizes[idx_e] / 2;
    const int eblocks = (E + 255) / 256;

    detect_kernel<<<1, 32>>>((const long long*)ei);

    // --- CSR build ---
    zero_cnt_kernel<<<(NN + 255) / 256, 256>>>();
    hist_kernel<<<eblocks, 256>>>(ei, E);
    bsum_kernel<<<NBLK, SCAN_B>>>();
    bscan_kernel<<<1, 128>>>();
    scan2_kernel<<<NBLK, SCAN_B>>>();
    reorder_kernel<<<eblocks, 256>>>(ei, E);

    // --- aggregate (fuses init) ---
    gather_kernel<<<(NN * 32 + 255) / 256, 256>>>(x, eps);

    // --- MLP + BN ---
    const int gblocks = (NN + BM - 1) / BM;
    gemm1_kernel<<<gblocks, 256>>>(W1, b1);
    finalize_kernel<<<1, FDIM>>>(gamma, beta);
    gemm2_kernel<<<gblocks, 256>>>(W2, b2, out);
}

// round 8
// speedup vs baseline: 2.6243x; 1.1640x over previous
#include <cuda_runtime.h>
#include <cuda_bf16.h>
#include <cstdint>

#define NN 100000
#define FDIM 128
#define BM 128
#define BKK 32
#define SSTRIDE 36   // BKK + 4 -> conflict-free LDS (4*gid+tig); 144B rows keep 16B align
#define EMAX 1600000
#define SCAN_B 1024
#define NBLK ((NN + SCAN_B - 1) / SCAN_B)   // 98

// ---- scratch (device globals: allowed; no runtime allocation) ----
__device__ float g_agg[(size_t)NN * FDIM];
__device__ float g_h[(size_t)NN * FDIM];
__device__ float g_sum[FDIM];
__device__ float g_sq[FDIM];
__device__ float g_scale[FDIM];
__device__ float g_shift[FDIM];
__device__ int   g_ei64;
__device__ int   g_cnt[NN];
__device__ int   g_rowptr[NN + 1];
__device__ int   g_bsum[NBLK];
__device__ int   g_boff[NBLK];
__device__ int   g_src[EMAX];

// ---------------------------------------------------------------------------
__device__ __forceinline__ uint32_t f2tf32(float f) {
    uint32_t u;
    asm("cvt.rna.tf32.f32 %0, %1;" : "=r"(u) : "f"(f));
    return u;
}

__device__ __forceinline__ void mma_tf32(float c[4],
                                         uint32_t a0, uint32_t a1, uint32_t a2, uint32_t a3,
                                         uint32_t b0, uint32_t b1) {
    asm volatile(
        "mma.sync.aligned.m16n8k8.row.col.f32.tf32.tf32.f32 "
        "{%0,%1,%2,%3}, {%4,%5,%6,%7}, {%8,%9}, {%0,%1,%2,%3};"
        : "+f"(c[0]), "+f"(c[1]), "+f"(c[2]), "+f"(c[3])
        : "r"(a0), "r"(a1), "r"(a2), "r"(a3), "r"(b0), "r"(b1));
}

__device__ __forceinline__ void cp_async16(void* smem_dst, const void* gmem_src, int bytes) {
    uint32_t d = (uint32_t)__cvta_generic_to_shared(smem_dst);
    asm volatile("cp.async.ca.shared.global [%0], [%1], 16, %2;"
                 :: "r"(d), "l"(gmem_src), "r"(bytes) : "memory");
}

__device__ __forceinline__ int edge_at(const void* ei_raw, long long pos) {
    if (g_ei64) return (int)__ldg(((const long long*)ei_raw) + pos);
    return __ldg(((const int*)ei_raw) + pos);
}

// ---------------------------------------------------------------------------
// Kernel 0: zero counters + probe edge dtype (block 0 / thread 0)
// ---------------------------------------------------------------------------
__global__ __launch_bounds__(256) void zero_detect_kernel(const long long* __restrict__ ei) {
    int i = blockIdx.x * 256 + threadIdx.x;
    if (i < NN) g_cnt[i] = 0;
    if (i == 0) {
        int ok64 = 1;
        for (int k = 0; k < 64; ++k) {
            long long v = ei[k];
            if (v < 0 || v >= NN) { ok64 = 0; break; }
        }
        g_ei64 = ok64;
    }
}

// ---------------------------------------------------------------------------
// CSR build
// ---------------------------------------------------------------------------
__global__ __launch_bounds__(256) void hist_kernel(const void* __restrict__ ei, int E) {
    int e = blockIdx.x * 256 + threadIdx.x;
    if (e >= E) return;
    int r = edge_at(ei, e);
    if ((unsigned)r < NN) atomicAdd(&g_cnt[r], 1);
}

__global__ __launch_bounds__(SCAN_B) void bsum_kernel() {
    __shared__ int sm[32];
    int tid = threadIdx.x, lane = tid & 31, wid = tid >> 5;
    int i = blockIdx.x * SCAN_B + tid;
    int v = (i < NN) ? g_cnt[i] : 0;
#pragma unroll
    for (int o = 16; o; o >>= 1) v += __shfl_xor_sync(~0u, v, o);
    if (lane == 0) sm[wid] = v;
    __syncthreads();
    if (wid == 0) {
        int w = sm[lane];
#pragma unroll
        for (int o = 16; o; o >>= 1) w += __shfl_xor_sync(~0u, w, o);
        if (lane == 0) g_bsum[blockIdx.x] = w;
    }
}

__global__ __launch_bounds__(128) void bscan_kernel() {
    int tid = threadIdx.x;
    if (tid < FDIM) { g_sum[tid] = 0.f; g_sq[tid] = 0.f; }
    if (tid == 0) {
        int run = 0;
        for (int b = 0; b < NBLK; ++b) { g_boff[b] = run; run += g_bsum[b]; }
        g_rowptr[NN] = run;
    }
}

__global__ __launch_bounds__(SCAN_B) void scan2_kernel() {
    __shared__ int wsum[32];
    int tid = threadIdx.x, lane = tid & 31, wid = tid >> 5;
    int i = blockIdx.x * SCAN_B + tid;
    int v = (i < NN) ? g_cnt[i] : 0;
    int incl = v;
#pragma unroll
    for (int o = 1; o < 32; o <<= 1) {
        int t = __shfl_up_sync(~0u, incl, o);
        if (lane >= o) incl += t;
    }
    if (lane == 31) wsum[wid] = incl;
    __syncthreads();
    if (wid == 0) {
        int wv = wsum[lane];
        int winc = wv;
#pragma unroll
        for (int o = 1; o < 32; o <<= 1) {
            int t = __shfl_up_sync(~0u, winc, o);
            if (lane >= o) winc += t;
        }
        wsum[lane] = winc - wv;
    }
    __syncthreads();
    if (i < NN) {
        int excl = incl - v + wsum[wid] + g_boff[blockIdx.x];
        g_rowptr[i] = excl;
        g_cnt[i] = excl;
    }
}

__global__ __launch_bounds__(256) void reorder_kernel(const void* __restrict__ ei, int E) {
    int e = blockIdx.x * 256 + threadIdx.x;
    if (e >= E) return;
    int r = edge_at(ei, e);
    int c = edge_at(ei, (long long)E + e);
    if ((unsigned)r >= NN || (unsigned)c >= NN) return;
    int pos = atomicAdd(&g_cnt[r], 1);
    if ((unsigned)pos < EMAX) g_src[pos] = c;
}

// ---------------------------------------------------------------------------
// Gather-accumulate: one warp per destination node, unroll-4 for MLP.
// ---------------------------------------------------------------------------
__global__ __launch_bounds__(256) void gather_kernel(const float* __restrict__ x,
                                                     const float* __restrict__ eps) {
    int gw = (blockIdx.x * 256 + threadIdx.x) >> 5;
    int lane = threadIdx.x & 31;
    if (gw >= NN) return;
    int beg = __ldg(&g_rowptr[gw]);
    int end = __ldg(&g_rowptr[gw + 1]);
    float cc = 1.0f + __ldg(eps);
    float4 v = __ldg(((const float4*)(x + (size_t)gw * FDIM)) + lane);
    float4 acc = make_float4(v.x * cc, v.y * cc, v.z * cc, v.w * cc);
    int j = beg;
    for (; j + 4 <= end; j += 4) {
        int s0 = __ldg(&g_src[j]);
        int s1 = __ldg(&g_src[j + 1]);
        int s2 = __ldg(&g_src[j + 2]);
        int s3 = __ldg(&g_src[j + 3]);
        float4 a = __ldg(((const float4*)(x + (size_t)s0 * FDIM)) + lane);
        float4 b = __ldg(((const float4*)(x + (size_t)s1 * FDIM)) + lane);
        float4 c = __ldg(((const float4*)(x + (size_t)s2 * FDIM)) + lane);
        float4 d = __ldg(((const float4*)(x + (size_t)s3 * FDIM)) + lane);
        acc.x += (a.x + b.x) + (c.x + d.x);
        acc.y += (a.y + b.y) + (c.y + d.y);
        acc.z += (a.z + b.z) + (c.z + d.z);
        acc.w += (a.w + b.w) + (c.w + d.w);
    }
    for (; j < end; ++j) {
        int s0 = __ldg(&g_src[j]);
        float4 a = __ldg(((const float4*)(x + (size_t)s0 * FDIM)) + lane);
        acc.x += a.x; acc.y += a.y; acc.z += a.z; acc.w += a.w;
    }
    ((float4*)(g_agg + (size_t)gw * FDIM))[lane] = acc;
}

// ---------------------------------------------------------------------------
// Kernel 3: GEMM1 (tf32, cp.async double-buffered)  h = agg @ W1^T + b1 + BN stats
// ---------------------------------------------------------------------------
__global__ __launch_bounds__(256) void gemm1_kernel(const float* __restrict__ W1,
                                                    const float* __restrict__ b1) {
    __shared__ float s_a[2][BM][SSTRIDE];
    __shared__ float s_w[2][FDIM][SSTRIDE];
    __shared__ float sh_sum[FDIM];
    __shared__ float sh_sq[FDIM];

    const int tid  = threadIdx.x;
    const int lane = tid & 31;
    const int wid  = tid >> 5;
    const int wm   = wid >> 1;
    const int wn   = wid & 1;
    const int gid  = lane >> 2;
    const int tig  = lane & 3;
    const int row0 = blockIdx.x * BM;

    if (tid < FDIM) { sh_sum[tid] = 0.f; sh_sq[tid] = 0.f; }

    // tile loader: stage s gets K-columns [kt, kt+32)
    auto load_tile = [&](int kt, int s) {
#pragma unroll
        for (int it = 0; it < 4; ++it) {
            int idx = it * 256 + tid;       // 0..1023
            int r   = idx >> 3;             // 0..127
            int kk  = (idx & 7) * 4;        // 0..28
            int grow = row0 + r;
            const float* asrc = (grow < NN)
                ? &g_agg[(size_t)grow * FDIM + kt + kk] : g_agg;
            cp_async16(&s_a[s][r][kk], asrc, (grow < NN) ? 16 : 0);
            cp_async16(&s_w[s][r][kk], &W1[(size_t)r * FDIM + kt + kk], 16);
        }
        asm volatile("cp.async.commit_group;" ::: "memory");
    };

    float c[2][8][4];
#pragma unroll
    for (int mt = 0; mt < 2; ++mt)
#pragma unroll
        for (int nt = 0; nt < 8; ++nt)
#pragma unroll
            for (int j = 0; j < 4; ++j) c[mt][nt][j] = 0.f;

    load_tile(0, 0);
#pragma unroll
    for (int kti = 0; kti < 4; ++kti) {
        const int s = kti & 1;
        if (kti < 3) load_tile((kti + 1) * BKK, 1 - s);
        if (kti < 3) asm volatile("cp.async.wait_group 1;" ::: "memory");
        else         asm volatile("cp.async.wait_group 0;" ::: "memory");
        __syncthreads();

#pragma unroll
        for (int ks = 0; ks < 4; ++ks) {
            int k0 = ks * 8;
            uint32_t af[2][4];
#pragma unroll
            for (int mt = 0; mt < 2; ++mt) {
                int rb = wm * 32 + mt * 16 + gid;
                af[mt][0] = f2tf32(s_a[s][rb][k0 + tig]);
                af[mt][1] = f2tf32(s_a[s][rb + 8][k0 + tig]);
                af[mt][2] = f2tf32(s_a[s][rb][k0 + tig + 4]);
                af[mt][3] = f2tf32(s_a[s][rb + 8][k0 + tig + 4]);
            }
#pragma unroll
            for (int nt = 0; nt < 8; ++nt) {
                int nb = wn * 64 + nt * 8 + gid;
                uint32_t bb0 = f2tf32(s_w[s][nb][k0 + tig]);
                uint32_t bb1 = f2tf32(s_w[s][nb][k0 + tig + 4]);
                mma_tf32(c[0][nt], af[0][0], af[0][1], af[0][2], af[0][3], bb0, bb1);
                mma_tf32(c[1][nt], af[1][0], af[1][1], af[1][2], af[1][3], bb0, bb1);
            }
        }
        __syncthreads();   // protect stage s before it is refilled two iters later
    }

    // epilogue: bias, store h, accumulate BN stats
    float psum[8][2], psq[8][2];
#pragma unroll
    for (int nt = 0; nt < 8; ++nt) {
        psum[nt][0] = 0.f; psum[nt][1] = 0.f;
        psq[nt][0] = 0.f;  psq[nt][1] = 0.f;
    }

#pragma unroll
    for (int nt = 0; nt < 8; ++nt) {
        int col = wn * 64 + nt * 8 + 2 * tig;
        float2 bb = __ldg((const float2*)&b1[col]);
#pragma unroll
        for (int mt = 0; mt < 2; ++mt) {
            int r0g = row0 + wm * 32 + mt * 16 + gid;
            if (r0g < NN) {
                float h0 = c[mt][nt][0] + bb.x;
                float h1 = c[mt][nt][1] + bb.y;
                *(float2*)&g_h[(size_t)r0g * FDIM + col] = make_float2(h0, h1);
                psum[nt][0] += h0; psum[nt][1] += h1;
                psq[nt][0] += h0 * h0; psq[nt][1] += h1 * h1;
            }
            int r1g = r0g + 8;
            if (r1g < NN) {
                float h0 = c[mt][nt][2] + bb.x;
                float h1 = c[mt][nt][3] + bb.y;
                *(float2*)&g_h[(size_t)r1g * FDIM + col] = make_float2(h0, h1);
                psum[nt][0] += h0; psum[nt][1] += h1;
                psq[nt][0] += h0 * h0; psq[nt][1] += h1 * h1;
            }
        }
    }

#pragma unroll
    for (int off = 16; off >= 4; off >>= 1) {
#pragma unroll
        for (int nt = 0; nt < 8; ++nt) {
#pragma unroll
            for (int j = 0; j < 2; ++j) {
                psum[nt][j] += __shfl_xor_sync(0xffffffffu, psum[nt][j], off);
                psq[nt][j]  += __shfl_xor_sync(0xffffffffu, psq[nt][j], off);
            }
        }
    }
    if (gid == 0) {
#pragma unroll
        for (int nt = 0; nt < 8; ++nt) {
            int col = wn * 64 + nt * 8 + 2 * tig;
            atomicAdd(&sh_sum[col],     psum[nt][0]);
            atomicAdd(&sh_sum[col + 1], psum[nt][1]);
            atomicAdd(&sh_sq[col],      psq[nt][0]);
            atomicAdd(&sh_sq[col + 1],  psq[nt][1]);
        }
    }
    __syncthreads();
    if (tid < FDIM) {
        atomicAdd(&g_sum[tid], sh_sum[tid]);
        atomicAdd(&g_sq[tid],  sh_sq[tid]);
    }
}

// ---------------------------------------------------------------------------
__global__ void finalize_kernel(const float* __restrict__ gamma,
                                const float* __restrict__ beta) {
    int i = threadIdx.x;
    float invn = 1.0f / (float)NN;
    float mean = g_sum[i] * invn;
    float var = g_sq[i] * invn - mean * mean;
    float rstd = rsqrtf(var + 1e-5f);
    float sc = rstd * __ldg(&gamma[i]);
    g_scale[i] = sc;
    g_shift[i] = __ldg(&beta[i]) - mean * sc;
}

// ---------------------------------------------------------------------------
// Kernel 5: GEMM2 (tf32, cp.async double-buffered)
// out = relu(h*scale+shift) @ W2^T + b2 ; BN+relu applied at fragment load
// ---------------------------------------------------------------------------
__global__ __launch_bounds__(256) void gemm2_kernel(const float* __restrict__ W2,
                                                    const float* __restrict__ b2,
                                                    float* __restrict__ out) {
    __shared__ float s_a[2][BM][SSTRIDE];
    __shared__ float s_w[2][FDIM][SSTRIDE];
    __shared__ float ss_scale[FDIM];
    __shared__ float ss_shift[FDIM];

    const int tid  = threadIdx.x;
    const int lane = tid & 31;
    const int wid  = tid >> 5;
    const int wm   = wid >> 1;
    const int wn   = wid & 1;
    const int gid  = lane >> 2;
    const int tig  = lane & 3;
    const int row0 = blockIdx.x * BM;

    if (tid < FDIM) { ss_scale[tid] = g_scale[tid]; ss_shift[tid] = g_shift[tid]; }

    auto load_tile = [&](int kt, int s) {
#pragma unroll
        for (int it = 0; it < 4; ++it) {
            int idx = it * 256 + tid;
            int r   = idx >> 3;
            int kk  = (idx & 7) * 4;
            int grow = row0 + r;
            const float* asrc = (grow < NN)
                ? &g_h[(size_t)grow * FDIM + kt + kk] : g_h;
            cp_async16(&s_a[s][r][kk], asrc, (grow < NN) ? 16 : 0);
            cp_async16(&s_w[s][r][kk], &W2[(size_t)r * FDIM + kt + kk], 16);
        }
        asm volatile("cp.async.commit_group;" ::: "memory");
    };

    float c[2][8][4];
#pragma unroll
    for (int mt = 0; mt < 2; ++mt)
#pragma unroll
        for (int nt = 0; nt < 8; ++nt)
#pragma unroll
            for (int j = 0; j < 4; ++j) c[mt][nt][j] = 0.f;

    load_tile(0, 0);
#pragma unroll
    for (int kti = 0; kti < 4; ++kti) {
        const int s = kti & 1;
        if (kti < 3) load_tile((kti + 1) * BKK, 1 - s);
        if (kti < 3) asm volatile("cp.async.wait_group 1;" ::: "memory");
        else         asm volatile("cp.async.wait_group 0;" ::: "memory");
        __syncthreads();

        const int ktg = kti * BKK;
#pragma unroll
        for (int ks = 0; ks < 4; ++ks) {
            int k0 = ks * 8;
            int kg0 = ktg + k0 + tig;       // global k of fragment cols [0],[1]
            float sc0 = ss_scale[kg0],     sh0 = ss_shift[kg0];
            float sc1 = ss_scale[kg0 + 4], sh1 = ss_shift[kg0 + 4];
            uint32_t af[2][4];
#pragma unroll
            for (int mt = 0; mt < 2; ++mt) {
                int rb = wm * 32 + mt * 16 + gid;
                af[mt][0] = f2tf32(fmaxf(fmaf(s_a[s][rb][k0 + tig],     sc0, sh0), 0.f));
                af[mt][1] = f2tf32(fmaxf(fmaf(s_a[s][rb + 8][k0 + tig], sc0, sh0), 0.f));
                af[mt][2] = f2tf32(fmaxf(fmaf(s_a[s][rb][k0 + tig + 4],     sc1, sh1), 0.f));
                af[mt][3] = f2tf32(fmaxf(fmaf(s_a[s][rb + 8][k0 + tig + 4], sc1, sh1), 0.f));
            }
#pragma unroll
            for (int nt = 0; nt < 8; ++nt) {
                int nb = wn * 64 + nt * 8 + gid;
                uint32_t bb0 = f2tf32(s_w[s][nb][k0 + tig]);
                uint32_t bb1 = f2tf32(s_w[s][nb][k0 + tig + 4]);
                mma_tf32(c[0][nt], af[0][0], af[0][1], af[0][2], af[0][3], bb0, bb1);
                mma_tf32(c[1][nt], af[1][0], af[1][1], af[1][2], af[1][3], bb0, bb1);
            }
        }
        __syncthreads();
    }

#pragma unroll
    for (int nt = 0; nt < 8; ++nt) {
        int col = wn * 64 + nt * 8 + 2 * tig;
        float2 bb = __ldg((const float2*)&b2[col]);
#pragma unroll
        for (int mt = 0; mt < 2; ++mt) {
            int r0g = row0 + wm * 32 + mt * 16 + gid;
            if (r0g < NN) {
                *(float2*)&out[(size_t)r0g * FDIM + col] =
                    make_float2(c[mt][nt][0] + bb.x, c[mt][nt][1] + bb.y);
            }
            int r1g = r0g + 8;
            if (r1g < NN) {
                *(float2*)&out[(size_t)r1g * FDIM + col] =
                    make_float2(c[mt][nt][2] + bb.x, c[mt][nt][3] + bb.y);
            }
        }
    }
}

// ---------------------------------------------------------------------------
extern "C" void kernel_launch(void* const* d_in, const int* in_sizes, int n_in,
                              void* d_out, int out_size) {
    int idx_x = -1, idx_e = -1, idx_eps = -1;
    int mats[2] = {-1, -1}; int nm = 0;
    int vecs[4] = {-1, -1, -1, -1}; int nv = 0;
    for (int i = 0; i < n_in; ++i) {
        int s = in_sizes[i];
        if (s == NN * FDIM)             idx_x = i;
        else if (s == 1)                idx_eps = i;
        else if (s == FDIM * FDIM)      { if (nm < 2) mats[nm++] = i; }
        else if (s == FDIM)             { if (nv < 4) vecs[nv++] = i; }
        else                            idx_e = i;
    }

    const float* x     = (const float*)d_in[idx_x];
    const void*  ei    = d_in[idx_e];
    const float* eps   = (const float*)d_in[idx_eps];
    const float* W1    = (const float*)d_in[mats[0]];
    const float* W2    = (const float*)d_in[mats[1]];
    const float *b1, *gamma, *beta, *b2;
    if (idx_x == 0) {          // dict order: x, edge, eps, W1, b1, gamma, beta, W2, b2
        b1    = (const float*)d_in[vecs[0]];
        gamma = (const float*)d_in[vecs[1]];
        beta  = (const float*)d_in[vecs[2]];
        b2    = (const float*)d_in[vecs[3]];
    } else {                   // alphabetical order
        b1    = (const float*)d_in[vecs[0]];
        b2    = (const float*)d_in[vecs[1]];
        beta  = (const float*)d_in[vecs[2]];
        gamma = (const float*)d_in[vecs[3]];
    }
    float* out = (float*)d_out;

    const int E = in_sizes[idx_e] / 2;
    const int eblocks = (E + 255) / 256;

    zero_detect_kernel<<<(NN + 255) / 256, 256>>>((const long long*)ei);
    hist_kernel<<<eblocks, 256>>>(ei, E);
    bsum_kernel<<<NBLK, SCAN_B>>>();
    bscan_kernel<<<1, 128>>>();
    scan2_kernel<<<NBLK, SCAN_B>>>();
    reorder_kernel<<<eblocks, 256>>>(ei, E);

    gather_kernel<<<(NN * 32 + 255) / 256, 256>>>(x, eps);

    const int gblocks = (NN + BM - 1) / BM;
    gemm1_kernel<<<gblocks, 256>>>(W1, b1);
    finalize_kernel<<<1, FDIM>>>(gamma, beta);
    gemm2_kernel<<<gblocks, 256>>>(W2, b2, out);
}